// round 17
// baseline (speedup 1.0000x reference)
#include <cuda_runtime.h>
#include <cuda_bf16.h>

#define BB 8
#define NN 2048
#define CC 128
#define KK 512

typedef unsigned long long ull;
typedef unsigned int uint;

// ---------------- device scratch (no allocations allowed) ----------------
__device__ float g_s1[BB * NN];
__device__ float g_s2[BB * NN];
__device__ uint  g_maxs2i[BB];
__device__ float g_hp[BB * CC];
__device__ float g_xpart[256 * CC];
__device__ float g_wa[2 * CC];              // W@a1, W@a2
__device__ int   g_rank[BB * NN];
__device__ int   g_sel[BB * KK];
__device__ int   g_cnt[BB * 8];             // K-split completion counters
__device__ __align__(16) __nv_bfloat16 g_Whi[CC * CC];
__device__ __align__(16) __nv_bfloat16 g_Wlo[CC * CC];
// split-bf16 h (row-major [b][j][c])
__device__ __align__(16) __nv_bfloat16 g_hhi[(long)BB * NN * CC];
__device__ __align__(16) __nv_bfloat16 g_hlo[(long)BB * NN * CC];
// K-split partials (4 quarters)
__device__ __align__(16) float g_part[4L * BB * KK * CC];
__device__ float g_zp[4 * BB * KK];

__device__ __forceinline__ float lrelu(float v) { return fmaxf(v, 0.01f * v); }

__device__ __forceinline__ uint fkey(float f) {
    uint u = __float_as_uint(f);
    return (u & 0x80000000u) ? ~u : (u | 0x80000000u);
}
__device__ __forceinline__ float fdec(uint k) {
    uint u = (k & 0x80000000u) ? (k & 0x7FFFFFFFu) : ~k;
    return __uint_as_float(u);
}

__device__ __forceinline__ uint cvt2(float a, float b) {
    uint r;
    asm("cvt.rn.bf16x2.f32 %0, %1, %2;" : "=r"(r) : "f"(b), "f"(a));
    return r;
}

__device__ __forceinline__ float ex2f(float x) {
    float r;
    asm("ex2.approx.f32 %0, %1;" : "=f"(r) : "f"(x));
    return r;
}

__device__ __forceinline__ void mma_bf16(float* d, const uint* a, const uint* bfr) {
    asm("mma.sync.aligned.m16n8k16.row.col.f32.bf16.bf16.f32 "
        "{%0,%1,%2,%3}, {%4,%5,%6,%7}, {%8,%9}, {%0,%1,%2,%3};"
        : "+f"(d[0]), "+f"(d[1]), "+f"(d[2]), "+f"(d[3])
        : "r"(a[0]), "r"(a[1]), "r"(a[2]), "r"(a[3]), "r"(bfr[0]), "r"(bfr[1]));
}
__device__ __forceinline__ void ldsm4(uint* r, uint addr) {
    asm volatile("ldmatrix.sync.aligned.m8n8.x4.shared.b16 {%0,%1,%2,%3}, [%4];"
                 : "=r"(r[0]), "=r"(r[1]), "=r"(r[2]), "=r"(r[3]) : "r"(addr));
}
__device__ __forceinline__ void ldsm4t(uint* r, uint addr) {
    asm volatile("ldmatrix.sync.aligned.m8n8.x4.trans.shared.b16 {%0,%1,%2,%3}, [%4];"
                 : "=r"(r[0]), "=r"(r[1]), "=r"(r[2]), "=r"(r[3]) : "r"(addr));
}

#define L2E 1.44269504f

// ---------------------------------------------------------------------------
// k_wp: split W -> Whi/Wlo bf16; block 64 computes wa = W@a (exact fp32);
// block 0 zeroes g_maxs2i and g_cnt.
// ---------------------------------------------------------------------------
__global__ void __launch_bounds__(256) k_wp(const float* __restrict__ W,
                                            const float* __restrict__ a) {
    int t = threadIdx.x;
    if (blockIdx.x == 64) {
        if (t < 128) {
            float p1 = 0.f, p2 = 0.f;
            const float* wr = W + t * CC;
            for (int c = 0; c < CC; c += 4) {
                float4 wv = *(const float4*)(wr + c);
                float4 a1 = *(const float4*)(a + c);
                float4 a2 = *(const float4*)(a + CC + c);
                p1 += wv.x * a1.x + wv.y * a1.y + wv.z * a1.z + wv.w * a1.w;
                p2 += wv.x * a2.x + wv.y * a2.y + wv.z * a2.z + wv.w * a2.w;
            }
            g_wa[t] = p1;
            g_wa[CC + t] = p2;
        }
        return;
    }
    if (blockIdx.x == 0) {
        if (t < BB) g_maxs2i[t] = 0u;
        if (t >= 64 && t < 64 + BB * 8) g_cnt[t - 64] = 0;
    }
    int idx = blockIdx.x * 256 + t;
    float w = W[idx];
    __nv_bfloat16 hi = __float2bfloat16(w);
    __nv_bfloat16 lo = __float2bfloat16(w - __bfloat162float(hi));
    g_Whi[idx] = hi;
    g_Wlo[idx] = lo;
}

// ---------------------------------------------------------------------------
// k_h: h = x@W via tensor cores (3-pass split bf16), split-bf16 h store.
// Exact fp32 s1/s2 via s = x@(W@a); s2 max; x col partials (ct==0 only).
// grid (32 jt, 2 ct, BB), 512 thr (16 warps 4m x 4n, 16M x 16N tiles).
// smem ~108KB -> 2 blocks/SM.
// ---------------------------------------------------------------------------
#define HAPITCH 136
#define HBPITCH 72
#define HS_WHI 0
#define HS_WLO (128 * HBPITCH)
#define HS_AHI (2 * 128 * HBPITCH)
#define HS_ALO (2 * 128 * HBPITCH + 64 * HAPITCH)
#define HS_BF16 (2 * 128 * HBPITCH + 2 * 64 * HAPITCH)   // 35840 elems
#define HS_XS (HS_BF16 * 2)                               // byte offset of fp32 xs
#define HS_XPR (HS_XS + 64 * 132 * 4)
#define HS_WMX (HS_XPR + 512 * 4)
#define KH_SMEM (HS_WMX + 64 * 4)

__global__ void __launch_bounds__(512) k_h(const float* __restrict__ x) {
    extern __shared__ __align__(16) char SM[];
    __nv_bfloat16* Sb = (__nv_bfloat16*)SM;
    float* xs  = (float*)(SM + HS_XS);     // [64][132]
    float* xpr = (float*)(SM + HS_XPR);    // [512]
    uint* wmx  = (uint*)(SM + HS_WMX);     // [64]

    int t = threadIdx.x, warp = t >> 5, lane = t & 31;
    int wm = warp >> 2, wn = warp & 3;
    int jt = blockIdx.x, ct = blockIdx.y, b = blockIdx.z;
    long row0 = (long)b * NN + jt * 64;

    // ---- cp.async loads: x tile fp32 + Whi/Wlo (this ct half) ----
    {
        const float* xsrc = x + row0 * CC;
        uint xdst = (uint)__cvta_generic_to_shared(xs);
#pragma unroll
        for (int u = 0; u < 4; u++) {
            int idx = t + 512 * u;
            int row = idx >> 5, seg = idx & 31;
            asm volatile("cp.async.cg.shared.global [%0], [%1], 16;"
                         :: "r"(xdst + (row * 132 + seg * 4) * 4),
                            "l"(xsrc + (long)row * CC + seg * 4) : "memory");
        }
        uint whidst = (uint)__cvta_generic_to_shared(Sb + HS_WHI);
        uint wlodst = (uint)__cvta_generic_to_shared(Sb + HS_WLO);
#pragma unroll
        for (int u = 0; u < 2; u++) {
            int idx = t + 512 * u;
            int row = idx >> 3, seg = idx & 7;
            asm volatile("cp.async.cg.shared.global [%0], [%1], 16;"
                         :: "r"(whidst + (row * HBPITCH + seg * 8) * 2),
                            "l"(g_Whi + row * CC + ct * 64 + seg * 8) : "memory");
            asm volatile("cp.async.cg.shared.global [%0], [%1], 16;"
                         :: "r"(wlodst + (row * HBPITCH + seg * 8) * 2),
                            "l"(g_Wlo + row * CC + ct * 64 + seg * 8) : "memory");
        }
        asm volatile("cp.async.commit_group;" ::: "memory");
        asm volatile("cp.async.wait_group 0;" ::: "memory");
    }
    __syncthreads();

    // ---- convert x tile -> Ahi/Alo (split bf16) ----
    {
        int r = t >> 3, kb = (t & 7) * 16;
        __nv_bfloat16* Ah = Sb + HS_AHI + r * HAPITCH;
        __nv_bfloat16* Al = Sb + HS_ALO + r * HAPITCH;
        const float* xr = xs + r * 132 + kb;
#pragma unroll
        for (int p = 0; p < 8; p++) {
            float f0 = xr[2 * p], f1 = xr[2 * p + 1];
            uint hp = cvt2(f0, f1);
            float h0 = __uint_as_float(hp << 16);
            float h1 = __uint_as_float(hp & 0xffff0000u);
            uint lp = cvt2(f0 - h0, f1 - h1);
            *(uint*)(Ah + kb + 2 * p) = hp;
            *(uint*)(Al + kb + 2 * p) = lp;
        }
    }

    // ---- ct==0 extras: exact s1/s2, s2 block max, x col partials ----
    if (ct == 0) {
        int lrow = warp * 4 + (lane >> 3), l8 = lane & 7;
        float p1 = 0.f, p2 = 0.f;
#pragma unroll
        for (int u = 0; u < 4; u++) {
            float4 xv = *(const float4*)&xs[lrow * 132 + l8 * 16 + u * 4];
            float4 v1 = *(const float4*)&g_wa[l8 * 16 + u * 4];
            float4 v2 = *(const float4*)&g_wa[CC + l8 * 16 + u * 4];
            p1 += xv.x * v1.x + xv.y * v1.y + xv.z * v1.z + xv.w * v1.w;
            p2 += xv.x * v2.x + xv.y * v2.y + xv.z * v2.z + xv.w * v2.w;
        }
#pragma unroll
        for (int o = 1; o < 8; o <<= 1) {
            p1 += __shfl_xor_sync(0xffffffffu, p1, o);
            p2 += __shfl_xor_sync(0xffffffffu, p2, o);
        }
        if (l8 == 0) {
            g_s1[row0 + lrow] = p1;
            g_s2[row0 + lrow] = p2;
            wmx[lrow] = fkey(p2);
        }
        // x col partial sums: thread c = t&127, quarter qr = t>>7
        {
            int c = t & 127, qr = t >> 7;
            float s = 0.f;
#pragma unroll
            for (int r = qr * 16; r < qr * 16 + 16; r++) s += xs[r * 132 + c];
            xpr[t] = s;
        }
    }
    __syncthreads();

    if (ct == 0) {
        if (t < 128)
            g_xpart[(b * 32 + jt) * CC + t] =
                xpr[t] + xpr[t + 128] + xpr[t + 256] + xpr[t + 384];
        if (t == 0) {
            uint m = 0;
            for (int r = 0; r < 64; r++) m = max(m, wmx[r]);
            atomicMax(&g_maxs2i[b], m);
        }
    }

    // ---- MMA: 3-pass split, 8 kq steps ----
    float acc[2][4];
#pragma unroll
    for (int fn = 0; fn < 2; fn++)
#pragma unroll
        for (int z = 0; z < 4; z++) acc[fn][z] = 0.f;

    int lg = lane & 15, lh = lane >> 4;
    uint base = (uint)__cvta_generic_to_shared(Sb);
    uint sWhi = base + HS_WHI * 2, sWlo = base + HS_WLO * 2;
    uint sAhi = base + HS_AHI * 2, sAlo = base + HS_ALO * 2;

#pragma unroll
    for (int kq = 0; kq < 8; kq++) {
        uint ahi[4], alo[4], bhi[4], blo[4];
        uint ra = (uint)((wm * 16 + lg) * HAPITCH + kq * 16 + lh * 8) * 2;
        ldsm4(ahi, sAhi + ra);
        ldsm4(alo, sAlo + ra);
        uint rb = (uint)((kq * 16 + lg) * HBPITCH + wn * 16 + lh * 8) * 2;
        ldsm4t(bhi, sWhi + rb);
        ldsm4t(blo, sWlo + rb);
#pragma unroll
        for (int fn = 0; fn < 2; fn++) {
            mma_bf16(acc[fn], ahi, bhi + 2 * fn);
            mma_bf16(acc[fn], ahi, blo + 2 * fn);
            mma_bf16(acc[fn], alo, bhi + 2 * fn);
        }
    }

    // ---- epilogue: split-bf16 h store ----
    int g2 = lane >> 2, tig = lane & 3;
    long r0 = row0 + wm * 16 + g2;
    long r1 = r0 + 8;
#pragma unroll
    for (int fn = 0; fn < 2; fn++) {
        int c0 = ct * 64 + wn * 16 + fn * 8 + 2 * tig;
        uint hp = cvt2(acc[fn][0], acc[fn][1]);
        float h0 = __uint_as_float(hp << 16);
        float h1 = __uint_as_float(hp & 0xffff0000u);
        uint lp = cvt2(acc[fn][0] - h0, acc[fn][1] - h1);
        *(uint*)&g_hhi[r0 * CC + c0] = hp;
        *(uint*)&g_hlo[r0 * CC + c0] = lp;
        hp = cvt2(acc[fn][2], acc[fn][3]);
        h0 = __uint_as_float(hp << 16);
        h1 = __uint_as_float(hp & 0xffff0000u);
        lp = cvt2(acc[fn][2] - h0, acc[fn][3] - h1);
        *(uint*)&g_hhi[r1 * CC + c0] = hp;
        *(uint*)&g_hlo[r1 * CC + c0] = lp;
    }
}

// ---------------------------------------------------------------------------
// k_rank: full rank + scatter + hp in one launch.
// ---------------------------------------------------------------------------
__global__ void __launch_bounds__(256) k_rank(const float* __restrict__ W) {
    int b = blockIdx.y;
    int t = threadIdx.x;

    if (blockIdx.x == 32) {
        __shared__ float xm[128];
        __shared__ float part[256];
        int c = t & 127, half = t >> 7;
        float s = 0.f;
#pragma unroll
        for (int k = half * 16; k < half * 16 + 16; k++)
            s += g_xpart[(b * 32 + k) * CC + c];
        part[t] = s;
        __syncthreads();
        if (half == 0) xm[c] = (part[c] + part[c + 128]) * (1.0f / NN);
        __syncthreads();
        float acc = 0.f;
#pragma unroll 8
        for (int k = half * 64; k < half * 64 + 64; k++)
            acc = fmaf(xm[k], W[k * CC + c], acc);
        part[t] = acc;
        __syncthreads();
        if (half == 0) g_hp[b * CC + c] = fmaxf(part[c] + part[c + 128], 0.f);
        return;
    }

    __shared__ ull keys[NN];
    __shared__ int part[256];
    for (int q = t; q < NN; q += 256)
        keys[q] = ((ull)fkey(g_s1[b * NN + q]) << 11) | (unsigned)(NN - 1 - q);
    __syncthreads();

    int il = t & 63, jq = t >> 6;
    int i = blockIdx.x * 64 + il;
    ull me = keys[i];
    int cnt = 0;
    int j0 = jq * 512;
#pragma unroll 8
    for (int j = 0; j < 512; j++)
        cnt += (keys[j0 + j] > me) ? 1 : 0;
    part[t] = cnt;
    __syncthreads();
    if (jq == 0) {
        int rank = part[il] + part[il + 64] + part[il + 128] + part[il + 192];
        g_rank[b * NN + i] = rank;
        if (rank < KK) g_sel[b * KK + rank] = i;
    }
}

// ---------------------------------------------------------------------------
// k_gemm: P@h over one K-quarter + counter-based fused combine (last block
// of each (b,mt) quartet combines in fixed order -> deterministic).
// ---------------------------------------------------------------------------
#define APITCH 40
#define BPITCH 136
#define A_ELEMS (64 * APITCH)
#define B_ELEMS (32 * BPITCH)
#define STG_ELEMS (2 * A_ELEMS + 2 * B_ELEMS)
#define OFF_ALO A_ELEMS
#define OFF_BHI (2 * A_ELEMS)
#define OFF_BLO (2 * A_ELEMS + B_ELEMS)
#define NSTG 4
#define GEMM_SMEM (NSTG * STG_ELEMS * 2 + 2048 + 256 + 256 + 16)

__global__ void __launch_bounds__(512) k_gemm(float* __restrict__ out) {
    extern __shared__ __align__(16) char SM[];
    __nv_bfloat16* S = (__nv_bfloat16*)SM;
    float* s2s = (float*)(SM + NSTG * STG_ELEMS * 2);
    float* s1s = (float*)(SM + NSTG * STG_ELEMS * 2 + 2048);
    float* zs  = (float*)(SM + NSTG * STG_ELEMS * 2 + 2304);
    int* lastp = (int*)(SM + NSTG * STG_ELEMS * 2 + 2560);

    int t = threadIdx.x, warp = t >> 5, lane = t & 31;
    int wm = warp >> 2, wn = warp & 3;
    int mt = blockIdx.x;
    int ks = blockIdx.y, b = blockIdx.z;

    const __nv_bfloat16* srcB[2] = {
        g_hhi + ((long)b * NN + ks * 512) * CC,
        g_hlo + ((long)b * NN + ks * 512) * CC
    };

#define COPY_B(buf, chunk)                                                        \
    {                                                                             \
        _Pragma("unroll")                                                         \
        for (int arr = 0; arr < 2; arr++) {                                       \
            const __nv_bfloat16* sp = srcB[arr] + (long)(chunk) * 32 * CC;        \
            uint dbase = (uint)__cvta_generic_to_shared(                          \
                S + (buf) * STG_ELEMS + OFF_BHI + arr * B_ELEMS);                 \
            int row = t >> 4, seg = t & 15;                                       \
            asm volatile("cp.async.cg.shared.global [%0], [%1], 16;"              \
                         :: "r"(dbase + (row * BPITCH + seg * 8) * 2),            \
                            "l"(sp + (long)row * CC + seg * 8) : "memory");       \
        }                                                                         \
        asm volatile("cp.async.commit_group;" ::: "memory");                      \
    }

#define COMPUTE_A(buf, chunk)                                                     \
    {                                                                             \
        const float* s2c = s2s + (chunk) * 32;                                    \
        __nv_bfloat16* Ah = S + (buf) * STG_ELEMS + slot * APITCH;                \
        __nv_bfloat16* Al = Ah + OFF_ALO;                                         \
        _Pragma("unroll")                                                         \
        for (int p = 0; p < 2; p++) {                                             \
            int col = 2 * q + 16 * p;                                             \
            float2 sv = *(const float2*)(s2c + col);                              \
            float e0 = lrelu(s1v + sv.x);                                         \
            float e1 = lrelu(s1v + sv.y);                                         \
            float w0 = ex2f(fmaf(e0, L2E, nML2E));                                \
            float w1 = ex2f(fmaf(e1, L2E, nML2E));                                \
            zacc += w0 + w1;                                                      \
            uint hp = cvt2(w0, w1);                                               \
            float f0 = __uint_as_float(hp << 16);                                 \
            float f1 = __uint_as_float(hp & 0xffff0000u);                         \
            uint lp = cvt2(w0 - f0, w1 - f1);                                     \
            *(uint*)(Ah + col) = hp;                                              \
            *(uint*)(Al + col) = lp;                                              \
        }                                                                         \
    }

    float acc[4][4];
#pragma unroll
    for (int fn = 0; fn < 4; fn++)
#pragma unroll
        for (int z = 0; z < 4; z++) acc[fn][z] = 0.f;

    COPY_B(0, 0)
    COPY_B(1, 1)

    {
        if (t < 128) {
            const float4* s2src = (const float4*)(g_s2 + (long)b * NN + ks * 512);
            ((float4*)s2s)[t] = s2src[t];
        }
        if (t < 64) {
            int sel = g_sel[b * KK + mt * 64 + t];
            s1s[t] = g_s1[b * NN + sel];
        }
    }

    // fused fill (ks==0 only)
    if (ks == 0) {
        int i = mt * 256 + (t & 255);
        int half = t >> 8;
        if (g_rank[b * NN + i] >= KK) {
            float* ob = out + (long)b * CC * NN + i;
            const float* hpb = g_hp + b * CC + half * 64;
#pragma unroll 8
            for (int c = 0; c < 64; c++)
                ob[(long)(half * 64 + c) * NN] = hpb[c];
        }
    }
    __syncthreads();

    int slot = t >> 3, q = t & 7;
    float s1v = s1s[slot];
    float ms2 = fdec(g_maxs2i[b]);
    float M = lrelu(s1v + ms2);
    float nML2E = -M * L2E;
    float zacc = 0.f;

    COMPUTE_A(0, 0)

    int lg = lane & 15, lh = lane >> 4;

    for (int c = 0; c < 16; c++) {
        if (c + 1 < 16) COMPUTE_A((c + 1) & 3, c + 1)
        if (c + 2 < 16) COPY_B((c + 2) & 3, c + 2)

        if (c < 14) {
            asm volatile("cp.async.wait_group 2;" ::: "memory");
        } else if (c == 14) {
            asm volatile("cp.async.wait_group 1;" ::: "memory");
        } else {
            asm volatile("cp.async.wait_group 0;" ::: "memory");
        }
        __syncthreads();

        uint Sb = (uint)__cvta_generic_to_shared(S + (c & 3) * STG_ELEMS);
        uint sAhi = Sb, sAlo = Sb + OFF_ALO * 2;
        uint sBhi = Sb + OFF_BHI * 2, sBlo = Sb + OFF_BLO * 2;

#pragma unroll
        for (int kq = 0; kq < 2; kq++) {
            int k0 = kq * 16;
            uint ahi[4], alo[4], bhi[8], blo[8];
            uint ra = (uint)((wm * 16 + lg) * APITCH + k0 + lh * 8) * 2;
            ldsm4(ahi, sAhi + ra);
            ldsm4(alo, sAlo + ra);
            uint rb0 = (uint)((k0 + lg) * BPITCH + wn * 32 + lh * 8) * 2;
            uint rb1 = (uint)((k0 + lg) * BPITCH + wn * 32 + 16 + lh * 8) * 2;
            ldsm4t(bhi,     sBhi + rb0);
            ldsm4t(bhi + 4, sBhi + rb1);
            ldsm4t(blo,     sBlo + rb0);
            ldsm4t(blo + 4, sBlo + rb1);

#pragma unroll
            for (int fn = 0; fn < 4; fn++) {
                mma_bf16(acc[fn], ahi, bhi + 2 * fn);
                mma_bf16(acc[fn], ahi, blo + 2 * fn);
                mma_bf16(acc[fn], alo, bhi + 2 * fn);
            }
        }
    }
#undef COPY_B
#undef COMPUTE_A

    __syncthreads();
    zacc += __shfl_xor_sync(0xffffffffu, zacc, 1);
    zacc += __shfl_xor_sync(0xffffffffu, zacc, 2);
    zacc += __shfl_xor_sync(0xffffffffu, zacc, 4);
    if (q == 0) zs[slot] = zacc;
    __syncthreads();
    if (t < 64) g_zp[(ks * BB + b) * KK + mt * 64 + t] = zs[t];

    // raw partial store
    int g2 = lane >> 2, tig = lane & 3;
    float* pb = g_part + (((long)ks * BB + b) * KK + mt * 64) * CC;
    {
        int zslot = wm * 16 + g2;
#pragma unroll
        for (int fn = 0; fn < 4; fn++) {
            int c0 = wn * 32 + fn * 8 + 2 * tig;
            pb[(long)zslot * CC + c0]           = acc[fn][0];
            pb[(long)zslot * CC + c0 + 1]       = acc[fn][1];
            pb[(long)(zslot + 8) * CC + c0]     = acc[fn][2];
            pb[(long)(zslot + 8) * CC + c0 + 1] = acc[fn][3];
        }
    }

    // ---- fused combine: last block of the (b,mt) quartet does it ----
    __threadfence();
    if (t == 0) *lastp = atomicAdd(&g_cnt[b * 8 + mt], 1);
    __syncthreads();
    if (*lastp == 3) {
        __threadfence();
        int cslot = t >> 3;
        int cb = (t & 7) * 16;
        long pidx = ((long)b * KK + mt * 64 + cslot) * CC + cb;
        const long POFF = (long)BB * KK * CC;
        const float4* p0 = (const float4*)(g_part + pidx);
        const float4* p1 = (const float4*)(g_part + POFF + pidx);
        const float4* p2 = (const float4*)(g_part + 2 * POFF + pidx);
        const float4* p3 = (const float4*)(g_part + 3 * POFF + pidx);
        int zi = b * KK + mt * 64 + cslot;
        float z = 1.f / (((g_zp[zi] + g_zp[BB * KK + zi])
                        + g_zp[2 * BB * KK + zi]) + g_zp[3 * BB * KK + zi]);
        int i = g_sel[b * KK + mt * 64 + cslot];
        float* ob = out + (long)b * CC * NN + i;
#pragma unroll
        for (int u = 0; u < 4; u++) {
            float4 a = p0[u], c1 = p1[u], c2 = p2[u], c3 = p3[u];
            ob[(long)(cb + 4 * u + 0) * NN] = fmaxf((((a.x + c1.x) + c2.x) + c3.x) * z, 0.f);
            ob[(long)(cb + 4 * u + 1) * NN] = fmaxf((((a.y + c1.y) + c2.y) + c3.y) * z, 0.f);
            ob[(long)(cb + 4 * u + 2) * NN] = fmaxf((((a.z + c1.z) + c2.z) + c3.z) * z, 0.f);
            ob[(long)(cb + 4 * u + 3) * NN] = fmaxf((((a.w + c1.w) + c2.w) + c3.w) * z, 0.f);
        }
    }
}

// ---------------------------------------------------------------------------
extern "C" void kernel_launch(void* const* d_in, const int* in_sizes, int n_in,
                              void* d_out, int out_size) {
    const float* x = nullptr;
    const float* W = nullptr;
    const float* a = nullptr;
    for (int k = 0; k < n_in; k++) {
        if (in_sizes[k] == BB * NN * CC)      x = (const float*)d_in[k];
        else if (in_sizes[k] == CC * CC)      W = (const float*)d_in[k];
        else if (in_sizes[k] == 2 * CC)       a = (const float*)d_in[k];
    }
    float* out = (float*)d_out;

    static int smem_set = 0;
    if (!smem_set) {
        cudaFuncSetAttribute(k_gemm, cudaFuncAttributeMaxDynamicSharedMemorySize, GEMM_SMEM);
        cudaFuncSetAttribute(k_h, cudaFuncAttributeMaxDynamicSharedMemorySize, KH_SMEM);
        smem_set = 1;
    }

    k_wp   <<<65, 256>>>(W, a);
    k_h    <<<dim3(32, 2, BB), 512, KH_SMEM>>>(x);
    k_rank <<<dim3(33, BB), 256>>>(W);
    k_gemm <<<dim3(8, 4, BB), 512, GEMM_SMEM>>>(out);
}